// round 17
// baseline (speedup 1.0000x reference)
#include <cuda_runtime.h>
#include <cuda_fp16.h>
#include <cstdint>

#define Bsz 512
#define Tsz 256
#define Dsz 128
#define Hsz 512
#define GIN 768
#define TB  (Tsz*Bsz)          /* 131072 */
#define BH  (Bsz*Hsz)          /* 262144 */
#define NCTA 128

// loop-kernel smem layout (bytes)
#define OFF_WA   0u            /* 64 x 1040  Uz/Ur slice        */
#define OFF_WB   66560u        /* 32 x 1040  Un slice           */
#define OFF_W1A  99840u        /* 64 x 528   W1(z|r) slice      */
#define OFF_W1B  133632u       /* 32 x 528   W1n slice          */
#define OFF_WGH  150528u       /* 32 x 272   Wgh slice          */
#define OFF_ACT  159232u       /* 32 x 1040  hd / rh tile       */
#define OFF_ACT1 192512u       /* 32 x 528   x1 tile            */
#define OFF_ACTD 209408u       /* 32 x 272   delta tile         */
#define OFF_RED  218112u       /* 8 KB k-split reduction        */
#define SMEM_TOTAL 226304

// ---------------- scratch (__device__ globals: allocation-free) ----------------
__device__ float g_HD[BH];              // hd = gh*h (fp32)
__device__ float g_Z [BH];              // z gate
__device__ __half g_x1h[TB*256];        // [xt|m] fp16
__device__ __half g_dh [TB*128];        // delta fp16
__device__ __half g_hd_h[BH];           // hd fp16
__device__ __half g_rh_h[BH];           // r*hd fp16
__device__ __half g_Wh[3*Hsz*Hsz];      // hidden slices (hi only)
__device__ __half g_W1hh[3*Hsz*256];    // x|m slices (hi only)
__device__ __half g_Wghh[Hsz*128];      // Wgh (hi only)
__device__ unsigned g_bar[512];         // 16 group counters, 128B apart

// ---------------- small helpers ----------------
__device__ __forceinline__ float sigm(float x) { return 1.f / (1.f + expf(-x)); }
__device__ __forceinline__ uint32_t smem_u32(const void* p) {
    uint32_t a;
    asm("{ .reg .u64 t; cvta.to.shared.u64 t, %1; cvt.u32.u64 %0, t; }" : "=r"(a) : "l"(p));
    return a;
}
__device__ __forceinline__ void cpa16(uint32_t dst, const void* src) {
    asm volatile("cp.async.cg.shared.global [%0],[%1],16;" :: "r"(dst), "l"(src));
}
__device__ __forceinline__ void sts16(uint32_t a, uint4 v) {
    asm volatile("st.shared.v4.b32 [%0],{%1,%2,%3,%4};"
                 :: "r"(a), "r"(v.x), "r"(v.y), "r"(v.z), "r"(v.w));
}
__device__ __forceinline__ void ldsm4(uint32_t &r0, uint32_t &r1, uint32_t &r2,
                                      uint32_t &r3, uint32_t addr) {
    asm volatile("ldmatrix.sync.aligned.m8n8.x4.shared.b16 {%0,%1,%2,%3},[%4];"
                 : "=r"(r0), "=r"(r1), "=r"(r2), "=r"(r3) : "r"(addr));
}
__device__ __forceinline__ void mma_f16(float* d, const uint32_t* a,
                                        uint32_t b0, uint32_t b1) {
    asm volatile("mma.sync.aligned.m16n8k16.row.col.f32.f16.f16.f32 "
                 "{%0,%1,%2,%3},{%4,%5,%6,%7},{%8,%9},{%0,%1,%2,%3};"
                 : "+f"(d[0]), "+f"(d[1]), "+f"(d[2]), "+f"(d[3])
                 : "r"(a[0]), "r"(a[1]), "r"(a[2]), "r"(a[3]), "r"(b0), "r"(b1));
}

// ---------------- group barrier primitives (16 CTAs per group) ----------------
__device__ __forceinline__ void arrive_g(int g) {
    __syncthreads();
    if (threadIdx.x == 0) {
        asm volatile("red.release.gpu.global.add.u32 [%0],%1;"
                     :: "l"(g_bar + g * 32), "r"(1u) : "memory");
    }
}
__device__ __forceinline__ void wait_g(int g, unsigned target) {
    if (threadIdx.x == 0) {
        unsigned v;
        do {
            asm volatile("ld.acquire.gpu.global.u32 %0,[%1];"
                         : "=r"(v) : "l"(g_bar + g * 32) : "memory");
        } while (v < target);
    }
    __syncthreads();
}

// ---------------- K0: fused p0 (input decay staging) + weight split + bar -----
__global__ void p0prep_kernel(const float* __restrict__ x,  const float* __restrict__ xl,
                              const float* __restrict__ mk, const float* __restrict__ dl,
                              const float* __restrict__ xmean,
                              const float* __restrict__ Wgx, const float* __restrict__ bgx,
                              const float* __restrict__ Wz, const float* __restrict__ Wr,
                              const float* __restrict__ Wn, const float* __restrict__ Wgh) {
    int bx = blockIdx.x;
    if (bx < 65536) {
        int idx = bx * 256 + threadIdx.x;
        int d   = idx & 127;
        int row = idx >> 7;
        int t   = row >> 9;
        int b   = row & 511;
        size_t xi = ((size_t)b * Tsz + t) * Dsz + d;
        float dv = dl[xi], mv = mk[xi];
        float gx = expf(-fmaxf(0.f, dv * Wgx[d * Dsz + d] + bgx[d]));
        float xt = mv * x[xi] + (1.f - mv) * (gx * xl[xi] + (1.f - gx) * xmean[d]);
        g_x1h[(size_t)row * 256 + d]       = __float2half(xt);
        g_x1h[(size_t)row * 256 + 128 + d] = __float2half(mv);
        g_dh [(size_t)row * 128 + d]       = __float2half(dv);
    } else if (bx < 65536 + 4864) {
        int idx = (bx - 65536) * 256 + threadIdx.x;
        if (idx < 786432) {                 // hidden slices (hi only)
            int k = idx & 511, j = (idx >> 9) & 511, g = idx >> 18;
            const float* W = (g == 0) ? Wz : (g == 1) ? Wr : Wn;
            g_Wh[idx] = __float2half(W[(size_t)j * GIN + 128 + k]);
        } else if (idx < 786432 + 393216) { // x|m slices (hi only)
            int e = idx - 786432;
            int k = e & 255, j = (e >> 8) & 511, g = e >> 17;
            const float* W = (g == 0) ? Wz : (g == 1) ? Wr : Wn;
            int col = (k < 128) ? k : (512 + k);
            g_W1hh[e] = __float2half(W[(size_t)j * GIN + col]);
        } else if (idx < 786432 + 393216 + 65536) {
            int e = idx - 786432 - 393216;
            g_Wghh[e] = __float2half(Wgh[e]);
        }
    } else {
        g_bar[threadIdx.x] = 0u;
        g_bar[threadIdx.x + 256] = 0u;
    }
}

__global__ void dummy_kernel() {}

// ---------------- loop GEMM helpers (accumulating chains) ---------------------
// 16x16 warp tile, 8 chains. A rows stride strA, W rows stride strB.
template<int KS>
__device__ __forceinline__ void gemm_N2(float c[8][4], uint32_t Ab, int strA,
                                        uint32_t Wb, int strB, int k0,
                                        int l, int wr0, int wn0) {
    uint32_t aoff = Ab + (uint32_t)((wr0 + (l & 15)) * strA + ((l >> 4) * 8) * 2 + k0 * 2);
    uint32_t b1o  = Wb + (uint32_t)((wn0 + (l & 7)) * strB + (l >> 3) * 16 + k0 * 2);
    uint32_t b2o  = b1o + (uint32_t)(8 * strB);
    #pragma unroll
    for (int it = 0; it < KS / 2; it++) {
        uint32_t a0[4], a1[4], b1[4], b2[4];
        ldsm4(a0[0], a0[1], a0[2], a0[3], aoff + it * 64);
        ldsm4(a1[0], a1[1], a1[2], a1[3], aoff + it * 64 + 32);
        ldsm4(b1[0], b1[1], b1[2], b1[3], b1o + it * 64);
        ldsm4(b2[0], b2[1], b2[2], b2[3], b2o + it * 64);
        int p = (it & 1) * 4;
        mma_f16(c[p + 0], a0, b1[0], b1[1]);
        mma_f16(c[p + 1], a0, b2[0], b2[1]);
        mma_f16(c[p + 2], a1, b1[2], b1[3]);
        mma_f16(c[p + 3], a1, b2[2], b2[3]);
    }
}

// 16x8 warp tile, 4 chains.
template<int KS>
__device__ __forceinline__ void gemm_8(float c[4][4], uint32_t Ab, int strA,
                                       uint32_t Wb, int strB, int k0,
                                       int l, int wr0, int wn0) {
    uint32_t aoff = Ab + (uint32_t)((wr0 + (l & 15)) * strA + ((l >> 4) * 8) * 2 + k0 * 2);
    uint32_t boff = Wb + (uint32_t)((wn0 + (l & 7)) * strB + (l >> 3) * 16 + k0 * 2);
    #pragma unroll
    for (int it = 0; it < KS / 2; it++) {
        uint32_t a0[4], a1[4], b[4];
        ldsm4(a0[0], a0[1], a0[2], a0[3], aoff + it * 64);
        ldsm4(a1[0], a1[1], a1[2], a1[3], aoff + it * 64 + 32);
        ldsm4(b[0], b[1], b[2], b[3], boff + it * 64);
        int p = (it & 1) * 2;
        mma_f16(c[p],     a0, b[0], b[1]);
        mma_f16(c[p + 1], a1, b[2], b[3]);
    }
}

// stage 32xN fp16 tile (N halves/row, stride STR) via cp.async
template<int CH, int STR>   // CH = 16B chunks per row
__device__ __forceinline__ void stageT(uint32_t dst, const __half* __restrict__ src,
                                       int srcStride, int tid) {
    #pragma unroll
    for (int u = 0; u < (32 * CH + 511) / 512; u++) {
        int i = u * 512 + tid;
        if ((32 * CH) % 512 == 0 || i < 32 * CH) {
            int r = i / CH, s = i % CH;
            cpa16(dst + (uint32_t)(r * STR + s * 16), src + (size_t)r * srcStride + s * 8);
        }
    }
}

// ---------------- persistent recurrent loop kernel ----------------------------
__global__ __launch_bounds__(512, 1) void loop_kernel(
        const float* __restrict__ bz, const float* __restrict__ br,
        const float* __restrict__ bn, const float* __restrict__ bgh,
        float* __restrict__ out) {
    extern __shared__ char smem[];
    uint32_t sb = smem_u32(smem);
    int tid = threadIdx.x, cta = blockIdx.x;
    int wid = tid >> 5, l = tid & 31;

    int q = cta & 15;
    int gg0 = cta >> 4;                        // serves groups gg0 and gg0+8
    int sA  = q >> 3;                          // 0 = z, 1 = r
    int jA0 = (q & 7) * 64;
    int jB0 = q * 32;
    const __half* WAhi = g_Wh + (size_t)sA * Hsz * Hsz;
    const __half* WBhi = g_Wh + (size_t)2 * Hsz * Hsz;
    const __half* W1A  = g_W1hh + (size_t)sA * Hsz * 256;
    const __half* W1B  = g_W1hh + (size_t)2 * Hsz * 256;

    // one-time: weights into smem
    for (int i = tid; i < 4096; i += 512) {
        int r = i >> 6, s = i & 63;
        cpa16(sb + OFF_WA + r * 1040 + s * 16, WAhi + (size_t)(jA0 + r) * Hsz + s * 8);
    }
    for (int i = tid; i < 2048; i += 512) {
        int r = i >> 6, s = i & 63;
        cpa16(sb + OFF_WB + r * 1040 + s * 16, WBhi + (size_t)(jB0 + r) * Hsz + s * 8);
    }
    for (int i = tid; i < 2048; i += 512) {
        int r = i >> 5, s = i & 31;
        cpa16(sb + OFF_W1A + r * 528 + s * 16, W1A + (size_t)(jA0 + r) * 256 + s * 8);
    }
    for (int i = tid; i < 1024; i += 512) {
        int r = i >> 5, s = i & 31;
        cpa16(sb + OFF_W1B + r * 528 + s * 16, W1B + (size_t)(jB0 + r) * 256 + s * 8);
    }
    for (int i = tid; i < 512; i += 512) {
        int r = i >> 4, s = i & 15;
        cpa16(sb + OFF_WGH + r * 272 + s * 16, g_Wghh + (size_t)(jB0 + r) * 128 + s * 8);
    }
    asm volatile("cp.async.commit_group;" ::: "memory");
    asm volatile("cp.async.wait_group 0;" ::: "memory");

    __half zh = __float2half(0.f);
    for (int i = tid; i < 2048; i += 512) {
        int o = cta * 2048 + i;
        g_HD[o] = 0.f;
        g_hd_h[o] = zh;
    }
    int grp[2] = {gg0, gg0 + 8};
    unsigned tg[2] = {16u, 16u};
    arrive_g(grp[0]);
    arrive_g(grp[1]);

    // warp layouts
    int widA = wid & 7;
    int wr0A = (widA & 1) * 16, wn0A = (widA >> 1) * 16;
    int kA0  = (wid < 8) ? 0 : 256;            // hd GEMM K split
    int kA1  = (wid < 8) ? 0 : 128;            // x1 GEMM K split
    int widB = wid & 7;
    int wr0B = (widB & 1) * 16, wn0B = (widB >> 1) * 8;
    int kB0  = (wid < 8) ? 0 : 256;
    int kB1  = (wid < 8) ? 0 : 128;
    int kG0  = (wid < 8) ? 0 : 64;             // gh GEMM K split

    // per-thread biases (columns fixed across t)
    const float* bsA = sA ? br : bz;
    int colA = jA0 + wn0A + (l & 3) * 2;
    float bA[2][2];
    #pragma unroll
    for (int nf = 0; nf < 2; nf++) {
        bA[nf][0] = __ldg(bsA + colA + nf * 8);
        bA[nf][1] = __ldg(bsA + colA + nf * 8 + 1);
    }
    int colB = jB0 + wn0B + (l & 3) * 2;
    float bN[2] = {__ldg(bn + colB), __ldg(bn + colB + 1)};
    float bG[2] = {__ldg(bgh + colB), __ldg(bgh + colB + 1)};

    for (int t = 0; t < Tsz; t++) {
        bool last = (t == Tsz - 1);
        // ================== phase A for both groups ==========================
        #pragma unroll 1
        for (int pi = 0; pi < 2; pi++) {
            int g = grp[pi];
            int rA0 = g * 32;
            // barrier-independent: stage x1(t) tile pre-wait
            stageT<32, 528>(sb + OFF_ACT1, g_x1h + (size_t)(t * 512 + rA0) * 256, 256, tid);
            asm volatile("cp.async.commit_group;" ::: "memory");
            wait_g(g, tg[pi]); tg[pi] += 16;
            stageT<64, 1040>(sb + OFF_ACT, g_hd_h + (size_t)rA0 * Hsz, Hsz, tid);
            asm volatile("cp.async.commit_group;" ::: "memory");
            float2 hdv[2][2];
            if (wid < 8 && sA) {
                #pragma unroll
                for (int nf = 0; nf < 2; nf++)
                    #pragma unroll
                    for (int h = 0; h < 2; h++) {
                        int row = rA0 + wr0A + (l >> 2) + h * 8;
                        hdv[nf][h] = __ldcg((const float2*)(g_HD + (size_t)row * Hsz
                                                            + colA + nf * 8));
                    }
            }
            asm volatile("cp.async.wait_group 0;" ::: "memory");
            __syncthreads();
            float c[8][4];
            #pragma unroll
            for (int i = 0; i < 8; i++)
                #pragma unroll
                for (int j = 0; j < 4; j++) c[i][j] = 0.f;
            gemm_N2<16>(c, sb + OFF_ACT,  1040, sb + OFF_WA,  1040, kA0, l, wr0A, wn0A);
            gemm_N2<8> (c, sb + OFF_ACT1, 528,  sb + OFF_W1A, 528,  kA1, l, wr0A, wn0A);
            float d[2][4];
            #pragma unroll
            for (int i = 0; i < 4; i++) {
                d[0][i] = (c[0][i] + c[2][i]) + (c[4][i] + c[6][i]);
                d[1][i] = (c[1][i] + c[3][i]) + (c[5][i] + c[7][i]);
            }
            if (wid >= 8) {
                uint32_t ra = sb + OFF_RED + (uint32_t)(widA * 1024 + l * 32);
                uint4 v0 = {__float_as_uint(d[0][0]), __float_as_uint(d[0][1]),
                            __float_as_uint(d[0][2]), __float_as_uint(d[0][3])};
                uint4 v1 = {__float_as_uint(d[1][0]), __float_as_uint(d[1][1]),
                            __float_as_uint(d[1][2]), __float_as_uint(d[1][3])};
                sts16(ra, v0);
                sts16(ra + 16, v1);
            }
            __syncthreads();
            if (wid < 8) {
                uint32_t off = OFF_RED + (uint32_t)(widA * 1024 + l * 32);
                uint4 v0 = *(const uint4*)(smem + off);
                uint4 v1 = *(const uint4*)(smem + off + 16);
                d[0][0] += __uint_as_float(v0.x); d[0][1] += __uint_as_float(v0.y);
                d[0][2] += __uint_as_float(v0.z); d[0][3] += __uint_as_float(v0.w);
                d[1][0] += __uint_as_float(v1.x); d[1][1] += __uint_as_float(v1.y);
                d[1][2] += __uint_as_float(v1.z); d[1][3] += __uint_as_float(v1.w);
                #pragma unroll
                for (int nf = 0; nf < 2; nf++) {
                    #pragma unroll
                    for (int h = 0; h < 2; h++) {
                        int row = rA0 + wr0A + (l >> 2) + h * 8;
                        size_t o = (size_t)row * Hsz + colA + nf * 8;
                        float s0 = sigm(d[nf][h * 2]     + bA[nf][0]);
                        float s1 = sigm(d[nf][h * 2 + 1] + bA[nf][1]);
                        if (sA == 0) {
                            float2 zz = {s0, s1};
                            *(float2*)(g_Z + o) = zz;
                        } else {
                            __half2 hp;
                            hp.x = __float2half(s0 * hdv[nf][h].x);
                            hp.y = __float2half(s1 * hdv[nf][h].y);
                            *(__half2*)(g_rh_h + o) = hp;
                        }
                    }
                }
            }
            arrive_g(g);
        }

        // ================== phase B for both groups ==========================
        #pragma unroll 1
        for (int pi = 0; pi < 2; pi++) {
            int g = grp[pi];
            int rB0 = g * 32;
            // barrier-independent: x1(t), delta(t+1) tiles + g_HD prefetch
            stageT<32, 528>(sb + OFF_ACT1, g_x1h + (size_t)(t * 512 + rB0) * 256, 256, tid);
            if (!last)
                stageT<16, 272>(sb + OFF_ACTD,
                                g_dh + (size_t)((t + 1) * 512 + rB0) * 128, 128, tid);
            asm volatile("cp.async.commit_group;" ::: "memory");
            float2 hdv[2];
            if (wid < 8) {
                #pragma unroll
                for (int h = 0; h < 2; h++) {
                    int row = rB0 + wr0B + (l >> 2) + h * 8;
                    hdv[h] = __ldcg((const float2*)(g_HD + (size_t)row * Hsz + colB));
                }
            }
            wait_g(g, tg[pi]); tg[pi] += 16;
            stageT<64, 1040>(sb + OFF_ACT, g_rh_h + (size_t)rB0 * Hsz, Hsz, tid);
            asm volatile("cp.async.commit_group;" ::: "memory");
            float2 zv[2];
            if (wid < 8) {
                #pragma unroll
                for (int h = 0; h < 2; h++) {
                    int row = rB0 + wr0B + (l >> 2) + h * 8;
                    zv[h] = __ldcg((const float2*)(g_Z + (size_t)row * Hsz + colB));
                }
            }
            asm volatile("cp.async.wait_group 0;" ::: "memory");
            __syncthreads();
            float c[4][4], cg[4][4];
            #pragma unroll
            for (int i = 0; i < 4; i++)
                #pragma unroll
                for (int j = 0; j < 4; j++) { c[i][j] = 0.f; cg[i][j] = 0.f; }
            gemm_8<16>(c,  sb + OFF_ACT,  1040, sb + OFF_WB,  1040, kB0, l, wr0B, wn0B);
            gemm_8<8> (c,  sb + OFF_ACT1, 528,  sb + OFF_W1B, 528,  kB1, l, wr0B, wn0B);
            gemm_8<4> (cg, sb + OFF_ACTD, 272,  sb + OFF_WGH, 272,  kG0, l, wr0B, wn0B);
            float d[4], dg[4];
            #pragma unroll
            for (int i = 0; i < 4; i++) {
                d[i]  = (c[0][i]  + c[1][i])  + (c[2][i]  + c[3][i]);
                dg[i] = (cg[0][i] + cg[1][i]) + (cg[2][i] + cg[3][i]);
            }
            if (wid >= 8) {
                uint32_t ra = sb + OFF_RED + (uint32_t)(widB * 512 + l * 16);
                uint4 v = {__float_as_uint(d[0]), __float_as_uint(d[1]),
                           __float_as_uint(d[2]), __float_as_uint(d[3])};
                uint4 vg = {__float_as_uint(dg[0]), __float_as_uint(dg[1]),
                            __float_as_uint(dg[2]), __float_as_uint(dg[3])};
                sts16(ra, v);
                sts16(ra + 4096, vg);
            }
            __syncthreads();
            if (wid < 8) {
                uint32_t off = OFF_RED + (uint32_t)(widB * 512 + l * 16);
                uint4 v  = *(const uint4*)(smem + off);
                uint4 vg = *(const uint4*)(smem + off + 4096);
                d[0] += __uint_as_float(v.x);  d[1] += __uint_as_float(v.y);
                d[2] += __uint_as_float(v.z);  d[3] += __uint_as_float(v.w);
                dg[0] += __uint_as_float(vg.x); dg[1] += __uint_as_float(vg.y);
                dg[2] += __uint_as_float(vg.z); dg[3] += __uint_as_float(vg.w);
                #pragma unroll
                for (int h = 0; h < 2; h++) {
                    int row = rB0 + wr0B + (l >> 2) + h * 8;
                    size_t o = (size_t)row * Hsz + colB;
                    #pragma unroll
                    for (int q2 = 0; q2 < 2; q2++) {
                        float ht = tanhf(d[h * 2 + q2] + bN[q2]);
                        float z  = q2 ? zv[h].y : zv[h].x;
                        float hd = q2 ? hdv[h].y : hdv[h].x;
                        float hp = (1.f - z) * hd + z * ht;
                        if (last) {
                            out[o + q2] = hp;
                        } else {
                            float gh = expf(-fmaxf(0.f, dg[h * 2 + q2] + bG[q2]));
                            float hdn = gh * hp;
                            g_HD[o + q2] = hdn;
                            g_hd_h[o + q2] = __float2half(hdn);
                        }
                    }
                }
            }
            arrive_g(g);
        }
    }
}

// ---------------- launch ----------------
extern "C" void kernel_launch(void* const* d_in, const int* in_sizes, int n_in,
                              void* d_out, int out_size) {
    const float* x    = (const float*)d_in[0];
    const float* xl   = (const float*)d_in[1];
    const float* mk   = (const float*)d_in[2];
    const float* dl   = (const float*)d_in[3];
    const float* xm   = (const float*)d_in[4];
    const float* Wz   = (const float*)d_in[5];
    const float* bz   = (const float*)d_in[6];
    const float* Wr   = (const float*)d_in[7];
    const float* br   = (const float*)d_in[8];
    const float* Wn   = (const float*)d_in[9];
    const float* bn   = (const float*)d_in[10];
    const float* Wgx  = (const float*)d_in[11];
    const float* bgx  = (const float*)d_in[12];
    const float* Wgh  = (const float*)d_in[13];
    const float* bgh  = (const float*)d_in[14];

    static int smem_set = 0;
    if (!smem_set) {
        cudaFuncSetAttribute(loop_kernel,
                             cudaFuncAttributeMaxDynamicSharedMemorySize, SMEM_TOTAL);
        smem_set = 1;
    }

    p0prep_kernel<<<65536 + 4864 + 1, 256>>>(x, xl, mk, dl, xm, Wgx, bgx,
                                             Wz, Wr, Wn, Wgh);
    dummy_kernel<<<1, 32>>>();
    dummy_kernel<<<1, 32>>>();
    loop_kernel<<<NCTA, 512, SMEM_TOTAL>>>(bz, br, bn, bgh, (float*)d_out);
}